// round 8
// baseline (speedup 1.0000x reference)
#include <cuda_runtime.h>

// Fixed problem shapes
static constexpr int NP     = 128;           // partitions
static constexpr int Cc     = 32;            // key channels
static constexpr int Dd     = 128;           // value/query dim
static constexpr int Bb     = 4;
static constexpr int Ss     = 2048;
static constexpr int Kk     = 2;
static constexpr int NPAIRS = Bb * Ss * Kk;  // 16384
static constexpr int NTOK   = Bb * Ss;       // 8192

static constexpr int NTHR   = 1024;
static constexpr int NBLK   = 2 * NP;        // 256 blocks = (partition, half)
static constexpr int HALFN  = NPAIRS / 2;    // 8192 pairs per half
static constexpr int PER    = HALFN / 4 / NTHR;    // 2 int4 per thread
static constexpr int CAP    = 512;           // per-(p,half) capacity (mean 64, sigma 8)

// Persistent device state (fully rewritten / reset every launch).
__device__ float g_P[2 * NP * Dd];           // per-(half,partition) partial rows
// Two-level grid barrier: 32 group counters on distinct 256B-spaced L2 lines
// (parallel RMWs), one top counter, monotonic phase (replay-safe).
__device__ unsigned          g_grp[32 * 64]; // use [g*64]; zero-init, reset each use
__device__ unsigned          g_top = 0;
__device__ volatile unsigned g_bar_phase = 0;

// ---------------------------------------------------------------------------
// 256 blocks x 1024 threads, 2 CTAs/SM (regs capped at 32 by launch_bounds ->
// all 256 CTAs co-resident, spin barrier deadlock-free).
// Block (p,h):
//   Phase 1: scan half h of idx (2 int4/thread), two-level shfl scan ->
//            deterministic compaction of ~64 matching pair indices.
//   Phase 2 (fused): per match m, the owning warp loads the 32-float key row
//            (128B coalesced) AND the 512B value row concurrently; butterfly
//            shfl gives all lanes w = mean(keys row); FMA into float4 acc.
//            Transpose-smem + warp-shfl reduce -> g_P[h][p] row.
//   (prefetch q/idx for phase 3; barrier wait absorbs their DRAM latency)
//   -- two-level grid barrier --
//   Phase 3: out = (P0[i0]+P1[i0]+P0[i1]+P1[i1]) * q, exactly 1 float4/thread.
// ---------------------------------------------------------------------------
__global__ void __launch_bounds__(NTHR, 2) k_fused(
    const int*   __restrict__ idx,
    const float* __restrict__ keys,
    const float* __restrict__ values,
    const float* __restrict__ q,
    float*       __restrict__ out)
{
    __shared__ int      js[CAP];
    __shared__ int      wsum[32];
    __shared__ float4   red4[32][33];        // padded transpose buffer
    __shared__ unsigned entry_phase;

    const int p    = blockIdx.x >> 1;
    const int h    = blockIdx.x & 1;
    const int tid  = threadIdx.x;
    const int lane = tid & 31;
    const int wid  = tid >> 5;

    if (tid == 0) entry_phase = g_bar_phase;   // snapshot before any release

    // ---- Phase 1a: strided-coalesced idx load (2 int4/thread), count
    const int4* idx4 = (const int4*)idx + h * (HALFN / 4);
    int4 my[PER];
    int cnt = 0;
    #pragma unroll
    for (int i = 0; i < PER; i++) {
        my[i] = idx4[i * NTHR + tid];
        cnt += (my[i].x == p) + (my[i].y == p) + (my[i].z == p) + (my[i].w == p);
    }

    // ---- Phase 1b: two-level exclusive scan (warp shfl + 32-entry top)
    int inc = cnt;
    #pragma unroll
    for (int o = 1; o < 32; o <<= 1) {
        int v = __shfl_up_sync(0xFFFFFFFFu, inc, o);
        if (lane >= o) inc += v;
    }
    if (lane == 31) wsum[wid] = inc;
    __syncthreads();
    if (wid == 0) {
        int v = wsum[lane];
        #pragma unroll
        for (int o = 1; o < 32; o <<= 1) {
            int u = __shfl_up_sync(0xFFFFFFFFu, v, o);
            if (lane >= o) v += u;
        }
        wsum[lane] = v;                        // inclusive prefix of warp totals
    }
    __syncthreads();
    int n   = wsum[31];
    int pos = (wid ? wsum[wid - 1] : 0) + (inc - cnt);

    // ---- Phase 1c: emit matched pair indices (fixed deterministic order)
    #pragma unroll
    for (int i = 0; i < PER; i++) {
        const int j = h * HALFN + (i * NTHR + tid) * 4;
        if (my[i].x == p && pos < CAP) js[pos++] = j + 0;
        if (my[i].y == p && pos < CAP) js[pos++] = j + 1;
        if (my[i].z == p && pos < CAP) js[pos++] = j + 2;
        if (my[i].w == p && pos < CAP) js[pos++] = j + 3;
    }
    if (n > CAP) n = CAP;
    __syncthreads();

    // ---- Phase 2 (fused weights+gather): warp = slice, lane = d4.
    // Per match: key row (128B) + value row (512B) loaded concurrently;
    // butterfly shfl -> every lane holds w; float4 FMA. ~2 matches/warp.
    {
        const int slice = wid;                 // 32 warps = 32 slices
        const int d4    = lane;
        const float4* V4 = (const float4*)values;
        float4 acc = make_float4(0.f, 0.f, 0.f, 0.f);
        int m = slice;
        for (; m + 32 < n; m += 64) {          // 2 matches, all loads in flight
            const int j0 = js[m], j1 = js[m + 32];
            float  k0 = keys[(size_t)j0 * Cc + lane];
            float  k1 = keys[(size_t)j1 * Cc + lane];
            float4 v0 = V4[(j0 >> 1) * 32 + d4];
            float4 v1 = V4[(j1 >> 1) * 32 + d4];
            #pragma unroll
            for (int o = 16; o >= 1; o >>= 1) {
                k0 += __shfl_xor_sync(0xFFFFFFFFu, k0, o);
                k1 += __shfl_xor_sync(0xFFFFFFFFu, k1, o);
            }
            const float w0 = k0 * (1.0f / Cc);
            const float w1 = k1 * (1.0f / Cc);
            acc.x += w0 * v0.x + w1 * v1.x;
            acc.y += w0 * v0.y + w1 * v1.y;
            acc.z += w0 * v0.z + w1 * v1.z;
            acc.w += w0 * v0.w + w1 * v1.w;
        }
        for (; m < n; m += 32) {               // tail (warp-uniform condition)
            const int j0 = js[m];
            float  k0 = keys[(size_t)j0 * Cc + lane];
            float4 v0 = V4[(j0 >> 1) * 32 + d4];
            #pragma unroll
            for (int o = 16; o >= 1; o >>= 1)
                k0 += __shfl_xor_sync(0xFFFFFFFFu, k0, o);
            const float w0 = k0 * (1.0f / Cc);
            acc.x += w0 * v0.x; acc.y += w0 * v0.y;
            acc.z += w0 * v0.z; acc.w += w0 * v0.w;
        }
        red4[slice][d4] = acc;
        __syncthreads();
        // warp-transpose reduce: warp `wid` owns column d4=wid, lanes=slices
        float4 v = red4[lane][wid];
        #pragma unroll
        for (int o = 16; o >= 1; o >>= 1) {
            v.x += __shfl_down_sync(0xFFFFFFFFu, v.x, o);
            v.y += __shfl_down_sync(0xFFFFFFFFu, v.y, o);
            v.z += __shfl_down_sync(0xFFFFFFFFu, v.z, o);
            v.w += __shfl_down_sync(0xFFFFFFFFu, v.w, o);
        }
        if (lane == 0)
            ((float4*)g_P)[(h * NP + p) * 32 + wid] = v;
    }

    // ---- Prefetch phase-3 inputs (independent of g_P) before the barrier
    const int    base = blockIdx.x * NTHR + tid;   // 0 .. 262143, 1 f4/thread
    const int2   ii   = ((const int2*)idx)[base >> 5];
    const float4 qv   = ((const float4*)q)[base];

    // ---- Two-level grid barrier (8 arrivals/group x 32 groups, then 32 top)
    __syncthreads();
    if (tid == 0) {
        __threadfence();                           // publish g_P
        const unsigned tgt = entry_phase + 1;
        const int g = blockIdx.x >> 3;             // 32 groups of 8 blocks
        if (atomicAdd(&g_grp[g * 64], 1u) == 7u) {
            atomicExch(&g_grp[g * 64], 0u);        // reset for next replay
            if (atomicAdd(&g_top, 1u) == 31u) {
                atomicExch(&g_top, 0u);
                __threadfence();
                g_bar_phase = tgt;                 // release
            }
        }
        while (g_bar_phase < tgt) __nanosleep(32);
    }
    __syncthreads();

    // ---- Phase 3: one float4 per thread; P rows are L2-resident
    {
        const int d4 = base & 31;
        const float4* P0 = (const float4*)g_P;     // half-0 rows
        const float4* P1 = P0 + NP * (Dd / 4);     // half-1 rows
        float4 a0 = P0[ii.x * 32 + d4];
        float4 b0 = P1[ii.x * 32 + d4];
        float4 a1 = P0[ii.y * 32 + d4];
        float4 b1 = P1[ii.y * 32 + d4];
        float4 o;
        o.x = ((a0.x + b0.x) + (a1.x + b1.x)) * qv.x;
        o.y = ((a0.y + b0.y) + (a1.y + b1.y)) * qv.y;
        o.z = ((a0.z + b0.z) + (a1.z + b1.z)) * qv.z;
        o.w = ((a0.w + b0.w) + (a1.w + b1.w)) * qv.w;
        ((float4*)out)[base] = o;
    }
}

extern "C" void kernel_launch(void* const* d_in, const int* in_sizes, int n_in,
                              void* d_out, int out_size)
{
    const int*   idx     = (const int*)  d_in[0];  // [B,S,K] int32
    const float* keys    = (const float*)d_in[1];  // [B,S,K,C] f32
    const float* values  = (const float*)d_in[2];  // [B,S,D]   f32
    const float* queries = (const float*)d_in[3];  // [B,S,D]   f32
    float*       out     = (float*)d_out;          // [B,S,D]   f32

    (void)in_sizes; (void)n_in; (void)out_size;

    k_fused<<<NBLK, NTHR>>>(idx, keys, values, queries, out);
}

// round 9
// speedup vs baseline: 1.0201x; 1.0201x over previous
#include <cuda_runtime.h>
#include <cstdint>

// Fixed problem shapes
static constexpr int NP     = 128;           // partitions
static constexpr int Cc     = 32;            // key channels
static constexpr int Dd     = 128;           // value/query dim
static constexpr int Bb     = 4;
static constexpr int Ss     = 2048;
static constexpr int Kk     = 2;
static constexpr int NPAIRS = Bb * Ss * Kk;  // 16384
static constexpr int NTOK   = Bb * Ss;       // 8192

static constexpr int NTHR   = 1024;
static constexpr int NBLK   = 2 * NP;        // 256 blocks = (partition, half)
static constexpr int HALFN  = NPAIRS / 2;    // 8192 pairs per half
static constexpr int PER    = HALFN / 4 / NTHR;    // 2 int4 per thread
static constexpr int CAP    = 512;           // per-(p,half) capacity (mean 64, sigma 8)

// Persistent device state (fully rewritten / reset every launch).
__device__ float g_P[2 * NP * Dd];           // per-(half,partition) partial rows
__device__ unsigned          g_bar_count = 0;
__device__ volatile unsigned g_bar_phase = 0;  // monotonic across graph replays

__device__ __forceinline__ uint32_t smem_u32(const void* p) {
    return (uint32_t)__cvta_generic_to_shared(p);
}

// ---------------------------------------------------------------------------
// 256 blocks x 1024 threads, 2 CTAs/SM (regs capped at 32 -> all co-resident,
// spin barrier deadlock-free).
//   Entry:   cp.async this block's 16KB q tile into smem (overlaps ph 1-2).
//   Phase 1: scan half h of idx, two-level shfl scan -> compaction (~64).
//   Phase 1.5: w[m] = mean_c keys[j_m,:], 8 threads/row octet-shfl.
//   Phase 2: float4 gather thread=(slice,d4); transpose + warp-shfl reduce.
//   (prefetch phase-3 idx; grid barrier; cp.async wait -> free)
//   Phase 3: out = (P0[i0]+P1[i0]+P0[i1]+P1[i1]) * q_sm, 1 float4/thread.
// ---------------------------------------------------------------------------
__global__ void __launch_bounds__(NTHR, 2) k_fused(
    const int*   __restrict__ idx,
    const float* __restrict__ keys,
    const float* __restrict__ values,
    const float* __restrict__ q,
    float*       __restrict__ out)
{
    __shared__ int      js[CAP];
    __shared__ float    wls[CAP];
    __shared__ int      wsum[32];
    __shared__ float4   red4[32][33];        // padded transpose buffer
    __shared__ float4   q_sm[NTHR];          // 16 KB prefetched q tile
    __shared__ unsigned entry_phase;

    const int p    = blockIdx.x >> 1;
    const int h    = blockIdx.x & 1;
    const int tid  = threadIdx.x;
    const int lane = tid & 31;
    const int wid  = tid >> 5;
    const int base = blockIdx.x * NTHR + tid;  // phase-3 float4 index

    // ---- Entry: async-prefetch q tile (no registers held, overlaps ph 1-2)
    {
        const uint32_t dst = smem_u32(&q_sm[tid]);
        const float4*  src = (const float4*)q + base;
        asm volatile("cp.async.ca.shared.global [%0], [%1], 16;\n"
                     "cp.async.commit_group;\n"
                     :: "r"(dst), "l"(src) : "memory");
    }

    if (tid == 0) entry_phase = g_bar_phase;   // snapshot before any release

    // ---- Phase 1a: strided-coalesced idx load (2 int4/thread), count
    const int4* idx4 = (const int4*)idx + h * (HALFN / 4);
    int4 my[PER];
    int cnt = 0;
    #pragma unroll
    for (int i = 0; i < PER; i++) {
        my[i] = idx4[i * NTHR + tid];
        cnt += (my[i].x == p) + (my[i].y == p) + (my[i].z == p) + (my[i].w == p);
    }

    // ---- Phase 1b: two-level exclusive scan (warp shfl + 32-entry top)
    int inc = cnt;
    #pragma unroll
    for (int o = 1; o < 32; o <<= 1) {
        int v = __shfl_up_sync(0xFFFFFFFFu, inc, o);
        if (lane >= o) inc += v;
    }
    if (lane == 31) wsum[wid] = inc;
    __syncthreads();
    if (wid == 0) {
        int v = wsum[lane];
        #pragma unroll
        for (int o = 1; o < 32; o <<= 1) {
            int u = __shfl_up_sync(0xFFFFFFFFu, v, o);
            if (lane >= o) v += u;
        }
        wsum[lane] = v;                        // inclusive prefix of warp totals
    }
    __syncthreads();
    int n   = wsum[31];
    int pos = (wid ? wsum[wid - 1] : 0) + (inc - cnt);

    // ---- Phase 1c: emit matched pair indices (fixed deterministic order)
    #pragma unroll
    for (int i = 0; i < PER; i++) {
        const int j = h * HALFN + (i * NTHR + tid) * 4;
        if (my[i].x == p && pos < CAP) js[pos++] = j + 0;
        if (my[i].y == p && pos < CAP) js[pos++] = j + 1;
        if (my[i].z == p && pos < CAP) js[pos++] = j + 2;
        if (my[i].w == p && pos < CAP) js[pos++] = j + 3;
    }
    if (n > CAP) n = CAP;
    __syncthreads();

    // ---- Phase 1.5: weights, 8 threads per 128B key row, octet shfl.
    {
        const int lane8 = tid & 7;
        const int row8  = tid >> 3;
        for (int b = 0; b < n; b += NTHR / 8) {
            const int m = b + row8;
            float s = 0.f;
            if (m < n) {
                float4 v = ((const float4*)keys)[(size_t)js[m] * (Cc / 4) + lane8];
                s = (v.x + v.y) + (v.z + v.w);
            }
            s += __shfl_xor_sync(0xFFFFFFFFu, s, 1);
            s += __shfl_xor_sync(0xFFFFFFFFu, s, 2);
            s += __shfl_xor_sync(0xFFFFFFFFu, s, 4);
            if (m < n && lane8 == 0) wls[m] = s * (1.0f / Cc);
        }
    }
    __syncthreads();

    // ---- Phase 2: float4 gather, thread=(slice,d4); ~2 matches/thread.
    {
        const int slice = tid >> 5;
        const int d4    = tid & 31;
        const float4* V4 = (const float4*)values;
        float4 acc = make_float4(0.f, 0.f, 0.f, 0.f);
        for (int m = slice; m < n; m += 32) {
            const float w = wls[m];
            float4 v = V4[(js[m] >> 1) * 32 + d4];
            acc.x += w * v.x; acc.y += w * v.y;
            acc.z += w * v.z; acc.w += w * v.w;
        }
        red4[slice][d4] = acc;
        __syncthreads();
        // warp-transpose reduce: warp `wid` owns column d4=wid, lanes=slices
        float4 v = red4[lane][wid];
        #pragma unroll
        for (int o = 16; o >= 1; o >>= 1) {
            v.x += __shfl_down_sync(0xFFFFFFFFu, v.x, o);
            v.y += __shfl_down_sync(0xFFFFFFFFu, v.y, o);
            v.z += __shfl_down_sync(0xFFFFFFFFu, v.z, o);
            v.w += __shfl_down_sync(0xFFFFFFFFu, v.w, o);
        }
        if (lane == 0)
            ((float4*)g_P)[(h * NP + p) * 32 + wid] = v;
    }

    // ---- Prefetch phase-3 indices (L2-hot from phase 1) before the barrier
    const int2 ii = ((const int2*)idx)[base >> 5];

    // ---- Grid barrier (256 arrivals; all CTAs co-resident at 2/SM)
    __syncthreads();
    if (tid == 0) {
        __threadfence();                           // publish g_P
        const unsigned tgt = entry_phase + 1;
        if (atomicAdd(&g_bar_count, 1u) == NBLK - 1) {
            g_bar_count = 0;
            __threadfence();
            g_bar_phase = tgt;                     // release
        } else {
            while (g_bar_phase < tgt) __nanosleep(32);
        }
    }
    __syncthreads();

    // ---- Phase 3: one float4 per thread; P rows L2-resident, q from smem
    {
        asm volatile("cp.async.wait_group 0;\n" ::: "memory");  // long done
        const int d4 = base & 31;
        const float4* P0 = (const float4*)g_P;     // half-0 rows
        const float4* P1 = P0 + NP * (Dd / 4);     // half-1 rows
        float4 a0 = P0[ii.x * 32 + d4];
        float4 b0 = P1[ii.x * 32 + d4];
        float4 a1 = P0[ii.y * 32 + d4];
        float4 b1 = P1[ii.y * 32 + d4];
        float4 qv = q_sm[tid];
        float4 o;
        o.x = ((a0.x + b0.x) + (a1.x + b1.x)) * qv.x;
        o.y = ((a0.y + b0.y) + (a1.y + b1.y)) * qv.y;
        o.z = ((a0.z + b0.z) + (a1.z + b1.z)) * qv.z;
        o.w = ((a0.w + b0.w) + (a1.w + b1.w)) * qv.w;
        ((float4*)out)[base] = o;
    }
}

extern "C" void kernel_launch(void* const* d_in, const int* in_sizes, int n_in,
                              void* d_out, int out_size)
{
    const int*   idx     = (const int*)  d_in[0];  // [B,S,K] int32
    const float* keys    = (const float*)d_in[1];  // [B,S,K,C] f32
    const float* values  = (const float*)d_in[2];  // [B,S,D]   f32
    const float* queries = (const float*)d_in[3];  // [B,S,D]   f32
    float*       out     = (float*)d_out;          // [B,S,D]   f32

    (void)in_sizes; (void)n_in; (void)out_size;

    k_fused<<<NBLK, NTHR>>>(idx, keys, values, queries, out);
}